// round 16
// baseline (speedup 1.0000x reference)
#include <cuda_runtime.h>
#include <cuda_bf16.h>
#include <math.h>
#include <stdint.h>

#define SEQ 2048
#define DM 1024
#define NH 16
#define NKV 4
#define HDIM 64
#define NE 8
#define NI 3584
#define QKVN 1536
#define NSLOTS (2*SEQ)
#define NSPLIT 8
#define CHUNK 4

typedef __nv_bfloat16 bf16;

// ---------------- scratch (device globals; no allocations) ----------------
__device__ bf16  g_wqkv_bf[QKVN*DM];
__device__ bf16  g_wo_bf[DM*DM];
__device__ bf16  g_w1_bf[(size_t)NE*NI*DM];
__device__ bf16  g_w3_bf[(size_t)NE*NI*DM];
__device__ bf16  g_w2_bf[(size_t)NE*DM*NI];
__device__ bf16  g_hn_bf[SEQ*DM];
__device__ float g_q[NH*SEQ*HDIM];      // tf32-rounded, pre-scaled 0.125
__device__ float g_k[NKV*SEQ*HDIM];     // tf32-rounded
__device__ bf16  g_vt[NKV*HDIM*SEQ];    // bf16, transposed [kvh][d][t]
__device__ float g_po[(size_t)NSPLIT*NH*SEQ*HDIM];
__device__ float g_pm[NSPLIT*NH*SEQ];
__device__ float g_pl[NSPLIT*NH*SEQ];
__device__ bf16  g_y_bf[SEQ*DM];
__device__ float g_h[SEQ*DM];
__device__ bf16  g_hf_bf[SEQ*DM];
__device__ int   g_cnt[NE];
__device__ int   g_slot[NE*SEQ];
__device__ float g_wslot[NSLOTS];
__device__ bf16  g_gb[(size_t)NSLOTS*NI];

// ---------------- helpers ---------------------------------------------------
__device__ __forceinline__ uint32_t f2tf32(float f) {
    uint32_t r;
    asm("cvt.rna.tf32.f32 %0, %1;" : "=r"(r) : "f"(f));
    return r;
}
__device__ __forceinline__ void mma_tf32(float c[4],
    uint32_t a0, uint32_t a1, uint32_t a2, uint32_t a3,
    uint32_t b0, uint32_t b1)
{
    asm volatile(
        "mma.sync.aligned.m16n8k8.row.col.f32.tf32.tf32.f32 "
        "{%0,%1,%2,%3}, {%4,%5,%6,%7}, {%8,%9}, {%0,%1,%2,%3};"
        : "+f"(c[0]), "+f"(c[1]), "+f"(c[2]), "+f"(c[3])
        : "r"(a0), "r"(a1), "r"(a2), "r"(a3), "r"(b0), "r"(b1));
}
__device__ __forceinline__ void mma_bf16(float c[4],
    uint32_t a0, uint32_t a1, uint32_t a2, uint32_t a3,
    uint32_t b0, uint32_t b1)
{
    asm volatile(
        "mma.sync.aligned.m16n8k16.row.col.f32.bf16.bf16.f32 "
        "{%0,%1,%2,%3}, {%4,%5,%6,%7}, {%8,%9}, {%0,%1,%2,%3};"
        : "+f"(c[0]), "+f"(c[1]), "+f"(c[2]), "+f"(c[3])
        : "r"(a0), "r"(a1), "r"(a2), "r"(a3), "r"(b0), "r"(b1));
}
__device__ __forceinline__ void ldsm4(uint32_t r[4], uint32_t addr) {
    asm volatile("ldmatrix.sync.aligned.m8n8.x4.shared.b16 {%0,%1,%2,%3}, [%4];"
                 : "=r"(r[0]), "=r"(r[1]), "=r"(r[2]), "=r"(r[3]) : "r"(addr));
}
__device__ __forceinline__ void cpa(uint32_t dst, const void* src, int sz) {
    asm volatile("cp.async.cg.shared.global [%0], [%1], 16, %2;"
                 :: "r"(dst), "l"(src), "r"(sz));
}
__device__ __forceinline__ uint32_t packbf(float a, float b) {
    __nv_bfloat162 p = __floats2bfloat162_rn(a, b);
    return *(uint32_t*)&p;
}

// ---------------- fp32 -> bf16 convert --------------------------------------
__global__ void f2bf_kernel(const float4* __restrict__ s, uint2* __restrict__ d, int n4)
{
    int i = blockIdx.x * blockDim.x + threadIdx.x;
    if (i >= n4) return;
    float4 v = s[i];
    __nv_bfloat162 lo = __floats2bfloat162_rn(v.x, v.y);
    __nv_bfloat162 hi = __floats2bfloat162_rn(v.z, v.w);
    uint2 o;
    o.x = *(uint32_t*)&lo;
    o.y = *(uint32_t*)&hi;
    d[i] = o;
}

// ---------------- rmsnorm (bf16 out) ----------------------------------------
__global__ __launch_bounds__(256) void rmsnorm_kernel(
    const float* __restrict__ x, const float* __restrict__ w,
    bf16* __restrict__ obf)
{
    int row = blockIdx.x;
    int tid = threadIdx.x;
    const float4* xr = (const float4*)(x + (size_t)row*DM);
    float4 v = xr[tid];
    float ss = v.x*v.x + v.y*v.y + v.z*v.z + v.w*v.w;
    __shared__ float red[8];
    #pragma unroll
    for (int ofs = 16; ofs > 0; ofs >>= 1) ss += __shfl_down_sync(0xffffffffu, ss, ofs);
    if ((tid & 31) == 0) red[tid >> 5] = ss;
    __syncthreads();
    __shared__ float sr;
    if (tid == 0) {
        float t = 0.f;
        #pragma unroll
        for (int i = 0; i < 8; i++) t += red[i];
        sr = rsqrtf(t / (float)DM + 1e-5f);
    }
    __syncthreads();
    float r = sr;
    float4 wv = ((const float4*)w)[tid];
    float4 o;
    o.x = v.x*r*wv.x; o.y = v.y*r*wv.y; o.z = v.z*r*wv.z; o.w = v.w*r*wv.w;
    __nv_bfloat162 lo = __floats2bfloat162_rn(o.x, o.y);
    __nv_bfloat162 hi = __floats2bfloat162_rn(o.z, o.w);
    uint2 ob; ob.x = *(uint32_t*)&lo; ob.y = *(uint32_t*)&hi;
    *(uint2*)(obf + (size_t)row*DM + tid*4) = ob;
}

// ---------------- fused ffn rmsnorm + gating --------------------------------
__global__ __launch_bounds__(256) void rmsnorm_gate_kernel(
    const float* __restrict__ x, const float* __restrict__ w,
    const float* __restrict__ gw, bf16* __restrict__ obf)
{
    int row = blockIdx.x;
    int tid = threadIdx.x;
    const float4* xr = (const float4*)(x + (size_t)row*DM);
    float4 v = xr[tid];
    float ss = v.x*v.x + v.y*v.y + v.z*v.z + v.w*v.w;
    __shared__ float red[8];
    #pragma unroll
    for (int ofs = 16; ofs > 0; ofs >>= 1) ss += __shfl_down_sync(0xffffffffu, ss, ofs);
    if ((tid & 31) == 0) red[tid >> 5] = ss;
    __syncthreads();
    __shared__ float sr;
    if (tid == 0) {
        float t = 0.f;
        #pragma unroll
        for (int i = 0; i < 8; i++) t += red[i];
        sr = rsqrtf(t / (float)DM + 1e-5f);
    }
    __syncthreads();
    float r = sr;
    float4 wv = ((const float4*)w)[tid];
    float4 o;
    o.x = v.x*r*wv.x; o.y = v.y*r*wv.y; o.z = v.z*r*wv.z; o.w = v.w*r*wv.w;
    __nv_bfloat162 lo = __floats2bfloat162_rn(o.x, o.y);
    __nv_bfloat162 hi = __floats2bfloat162_rn(o.z, o.w);
    uint2 ob; ob.x = *(uint32_t*)&lo; ob.y = *(uint32_t*)&hi;
    *(uint2*)(obf + (size_t)row*DM + tid*4) = ob;

    float d[NE];
    #pragma unroll
    for (int e = 0; e < NE; e++) {
        float4 gv = ((const float4*)(gw + (size_t)e*DM))[tid];
        d[e] = o.x*gv.x + o.y*gv.y + o.z*gv.z + o.w*gv.w;
    }
    #pragma unroll
    for (int e = 0; e < NE; e++) {
        #pragma unroll
        for (int ofs = 16; ofs > 0; ofs >>= 1)
            d[e] += __shfl_down_sync(0xffffffffu, d[e], ofs);
    }
    __shared__ float red2[8][NE];
    if ((tid & 31) == 0) {
        #pragma unroll
        for (int e = 0; e < NE; e++) red2[tid >> 5][e] = d[e];
    }
    __syncthreads();
    if (tid == 0) {
        float lg[NE];
        #pragma unroll
        for (int e = 0; e < NE; e++) {
            float t = 0.f;
            #pragma unroll
            for (int wpi = 0; wpi < 8; wpi++) t += red2[wpi][e];
            lg[e] = t;
        }
        float mx = lg[0];
        #pragma unroll
        for (int i = 1; i < NE; i++) mx = fmaxf(mx, lg[i]);
        float p[NE]; float den = 0.f;
        #pragma unroll
        for (int i = 0; i < NE; i++) { p[i] = expf(lg[i]-mx); den += p[i]; }
        #pragma unroll
        for (int i = 0; i < NE; i++) p[i] /= den;
        int i1 = 0;
        #pragma unroll
        for (int i = 1; i < NE; i++) if (p[i] > p[i1]) i1 = i;
        int i2 = (i1 == 0) ? 1 : 0;
        #pragma unroll
        for (int i = 0; i < NE; i++) if (i != i1 && p[i] > p[i2]) i2 = i;
        float w1 = p[i1], w2 = p[i2];
        float sw2 = w1 + w2;
        w1 /= sw2; w2 /= sw2;
        int pos1 = atomicAdd(&g_cnt[i1], 1);
        g_slot[i1*SEQ + pos1] = 2*row;
        g_wslot[2*row] = w1;
        int pos2 = atomicAdd(&g_cnt[i2], 1);
        g_slot[i2*SEQ + pos2] = 2*row + 1;
        g_wslot[2*row+1] = w2;
    }
}

// ---------------- bf16 HMMA GEMM: C[M,N] = A @ B^T (+resid, dual store) -----
// 3-stage cp.async, single barrier per K-chunk. 96KB smem -> 2 CTA/SM.
#define GSTG 16384
__global__ __launch_bounds__(256) void gemm_bf(
    const bf16* __restrict__ A, const bf16* __restrict__ B,
    const float* __restrict__ resid, float* __restrict__ C,
    float* __restrict__ C2, int M, int N, int K)
{
    extern __shared__ char smem[];
    int m0 = blockIdx.y * 128, n0 = blockIdx.x * 128;
    int tid = threadIdx.x, warp = tid >> 5, lane = tid & 31;
    int wm = (warp >> 2) * 64, wn = (warp & 3) * 32;
    uint32_t sbase = (uint32_t)__cvta_generic_to_shared(smem);
    uint32_t aoff[3], boff[3];
    #pragma unroll
    for (int s = 0; s < 3; s++) {
        aoff[s] = sbase + s*GSTG;
        boff[s] = sbase + 3*GSTG + s*GSTG;
    }

    int lrow = tid >> 1;
    int lsg  = (tid & 1) * 4;
    const bf16* Arow = A + (size_t)(m0 + lrow) * K;
    const bf16* Brow = B + (size_t)(n0 + lrow) * K;
    uint32_t dsw = (uint32_t)lrow * 128u;
    int rxor = lrow & 7;

    float acc[4][4][4];
    #pragma unroll
    for (int i = 0; i < 4; i++)
        #pragma unroll
        for (int j = 0; j < 4; j++)
            #pragma unroll
            for (int q = 0; q < 4; q++) acc[i][j][q] = 0.f;

    int CC = K / 64;
    auto loadChunk = [&](int c) {
        int s = c % 3;
        const char* pa = (const char*)(Arow + c*64);
        const char* pb = (const char*)(Brow + c*64);
        #pragma unroll
        for (int i = 0; i < 4; i++) {
            int seg = lsg + i;
            uint32_t o = dsw + (uint32_t)((seg ^ rxor) * 16);
            cpa(aoff[s] + o, pa + seg*16, 16);
            cpa(boff[s] + o, pb + seg*16, 16);
        }
        asm volatile("cp.async.commit_group;" ::: "memory");
    };
    loadChunk(0);
    if (CC > 1) loadChunk(1);

    int lt = lane >> 3;
    int rl = lane & 7;
    int th = (lt & 1) * 8;
    int ts = lane >> 4;

    for (int c = 0; c < CC; c++) {
        if (c + 1 < CC) asm volatile("cp.async.wait_group 1;" ::: "memory");
        else            asm volatile("cp.async.wait_group 0;" ::: "memory");
        __syncthreads();
        if (c + 2 < CC) loadChunk(c + 2);

        uint32_t Ab = aoff[c % 3], Bb = boff[c % 3];
        #pragma unroll
        for (int kk = 0; kk < 4; kk++) {
            uint32_t af[4][4], bfm[2][4];
            #pragma unroll
            for (int i = 0; i < 4; i++) {
                int row = wm + i*16 + th + rl;
                int seg = 2*kk + ts;
                ldsm4(af[i], Ab + row*128 + ((seg ^ (row & 7)) << 4));
            }
            #pragma unroll
            for (int j = 0; j < 2; j++) {
                int nr = wn + j*16 + th + rl;
                int seg = 2*kk + ts;
                ldsm4(bfm[j], Bb + nr*128 + ((seg ^ (nr & 7)) << 4));
            }
            #pragma unroll
            for (int i = 0; i < 4; i++)
                #pragma unroll
                for (int jn = 0; jn < 4; jn++) {
                    int jj = jn >> 1, hi = jn & 1;
                    mma_bf16(acc[i][jn], af[i][0], af[i][1], af[i][2], af[i][3],
                             bfm[jj][hi], bfm[jj][hi+2]);
                }
        }
    }

    int g = lane >> 2, tg = lane & 3;
    #pragma unroll
    for (int i = 0; i < 4; i++) {
        int r0 = m0 + wm + i*16 + g;
        int r1 = r0 + 8;
        #pragma unroll
        for (int j = 0; j < 4; j++) {
            int c0 = n0 + wn + j*8 + tg*2;
            float2 v0; v0.x = acc[i][j][0]; v0.y = acc[i][j][1];
            float2 v1; v1.x = acc[i][j][2]; v1.y = acc[i][j][3];
            if (resid) {
                const float2 rv0 = *(const float2*)(resid + (size_t)r0*N + c0);
                const float2 rv1 = *(const float2*)(resid + (size_t)r1*N + c0);
                v0.x += rv0.x; v0.y += rv0.y;
                v1.x += rv1.x; v1.y += rv1.y;
            }
            *(float2*)(C + (size_t)r0*N + c0) = v0;
            *(float2*)(C + (size_t)r1*N + c0) = v1;
            if (C2) {
                *(float2*)(C2 + (size_t)r0*N + c0) = v0;
                *(float2*)(C2 + (size_t)r1*N + c0) = v1;
            }
        }
    }
}

// ---------------- QKV GEMM with fused RoPE/split epilogue -------------------
__device__ __forceinline__ void rope_write(
    int t, int c0, float vx, float vy, const float* __restrict__ freqs)
{
    if (c0 < DM) {
        int h = c0 >> 6, d = c0 & 63, p = d >> 1;
        float cs = freqs[((size_t)t*32 + p)*2 + 0];
        float sn = freqs[((size_t)t*32 + p)*2 + 1];
        float2 o;
        o.x = __uint_as_float(f2tf32((vx*cs - vy*sn) * 0.125f));
        o.y = __uint_as_float(f2tf32((vy*cs + vx*sn) * 0.125f));
        *(float2*)(g_q + ((size_t)h*SEQ + t)*HDIM + d) = o;
    } else if (c0 < DM + NKV*HDIM) {
        int c = c0 - DM;
        int kh = c >> 6, d = c & 63, p = d >> 1;
        float cs = freqs[((size_t)t*32 + p)*2 + 0];
        float sn = freqs[((size_t)t*32 + p)*2 + 1];
        float2 o;
        o.x = __uint_as_float(f2tf32(vx*cs - vy*sn));
        o.y = __uint_as_float(f2tf32(vy*cs + vx*sn));
        *(float2*)(g_k + ((size_t)kh*SEQ + t)*HDIM + d) = o;
    } else {
        int c = c0 - DM - NKV*HDIM;
        int vh = c >> 6, d = c & 63;
        g_vt[((size_t)(vh*HDIM + d  ))*SEQ + t] = __float2bfloat16(vx);
        g_vt[((size_t)(vh*HDIM + d+1))*SEQ + t] = __float2bfloat16(vy);
    }
}

__global__ __launch_bounds__(256) void gemm_qkv(
    const bf16* __restrict__ A, const bf16* __restrict__ B,
    const float* __restrict__ freqs)
{
    extern __shared__ char smem[];
    const int K = DM;
    int m0 = blockIdx.y * 128, n0 = blockIdx.x * 128;
    int tid = threadIdx.x, warp = tid >> 5, lane = tid & 31;
    int wm = (warp >> 2) * 64, wn = (warp & 3) * 32;
    uint32_t sbase = (uint32_t)__cvta_generic_to_shared(smem);
    uint32_t aoff[3], boff[3];
    #pragma unroll
    for (int s = 0; s < 3; s++) {
        aoff[s] = sbase + s*GSTG;
        boff[s] = sbase + 3*GSTG + s*GSTG;
    }

    int lrow = tid >> 1;
    int lsg  = (tid & 1) * 4;
    const bf16* Arow = A + (size_t)(m0 + lrow) * K;
    const bf16* Brow = B + (size_t)(n0 + lrow) * K;
    uint32_t dsw = (uint32_t)lrow * 128u;
    int rxor = lrow & 7;

    float acc[4][4][4];
    #pragma unroll
    for (int i = 0; i < 4; i++)
        #pragma unroll
        for (int j = 0; j < 4; j++)
            #pragma unroll
            for (int q = 0; q < 4; q++) acc[i][j][q] = 0.f;

    const int CC = K / 64;
    auto loadChunk = [&](int c) {
        int s = c % 3;
        const char* pa = (const char*)(Arow + c*64);
        const char* pb = (const char*)(Brow + c*64);
        #pragma unroll
        for (int i = 0; i < 4; i++) {
            int seg = lsg + i;
            uint32_t o = dsw + (uint32_t)((seg ^ rxor) * 16);
            cpa(aoff[s] + o, pa + seg*16, 16);
            cpa(boff[s] + o, pb + seg*16, 16);
        }
        asm volatile("cp.async.commit_group;" ::: "memory");
    };
    loadChunk(0);
    loadChunk(1);

    int lt = lane >> 3;
    int rl = lane & 7;
    int th = (lt & 1) * 8;
    int ts = lane >> 4;

    for (int c = 0; c < CC; c++) {
        if (c + 1 < CC) asm volatile("cp.async.wait_group 1;" ::: "memory");
        else            asm volatile("cp.async.wait_group 0;" ::: "memory");
        __syncthreads();
        if (c + 2 < CC) loadChunk(c + 2);

        uint32_t Ab = aoff[c % 3], Bb = boff[c % 3];
        #pragma unroll
        for (int kk = 0; kk < 4; kk++) {
            uint32_t af[4][4], bfm[2][4];
            #pragma unroll
            for (int i = 0; i < 4; i++) {
                int row = wm + i*16 + th + rl;
                int seg = 2*kk + ts;
                ldsm4(af[i], Ab + row*128 + ((seg ^ (row & 7)) << 4));
            }
            #pragma unroll
            for (int j = 0; j < 2; j++) {
                int nr = wn + j*16 + th + rl;
                int seg = 2*kk + ts;
                ldsm4(bfm[j], Bb + nr*128 + ((seg ^ (nr & 7)) << 4));
            }
            #pragma unroll
            for (int i = 0; i < 4; i++)
                #pragma unroll
                for (int jn = 0; jn < 4; jn++) {
                    int jj = jn >> 1, hi = jn & 1;
                    mma_bf16(acc[i][jn], af[i][0], af[i][1], af[i][2], af[i][3],
                             bfm[jj][hi], bfm[jj][hi+2]);
                }
        }
    }

    int g = lane >> 2, tg = lane & 3;
    #pragma unroll
    for (int i = 0; i < 4; i++) {
        int t0 = m0 + wm + i*16 + g;
        int t1 = t0 + 8;
        #pragma unroll
        for (int j = 0; j < 4; j++) {
            int c0 = n0 + wn + j*8 + tg*2;
            rope_write(t0, c0, acc[i][j][0], acc[i][j][1], freqs);
            rope_write(t1, c0, acc[i][j][2], acc[i][j][3], freqs);
        }
    }
}

// ---------------- fused MoE w1/w3 GEMM + silu*mul (bf16 out) ---------------
__global__ __launch_bounds__(256) void gemm_w13(
    const bf16* __restrict__ A, const bf16* __restrict__ B1,
    const bf16* __restrict__ B3)
{
    extern __shared__ char smem[];
    int e = blockIdx.z;
    int M = g_cnt[e];
    if ((int)blockIdx.y * 128 >= M) return;
    const int* sl = g_slot + e * SEQ;
    B1 += (size_t)e * NI * DM;
    B3 += (size_t)e * NI * DM;

    int m0 = blockIdx.y * 128, n0 = blockIdx.x * 128;
    int tid = threadIdx.x, warp = tid >> 5, lane = tid & 31;
    int wm = (warp >> 2) * 64, wn = (warp & 3) * 32;
    uint32_t sbase = (uint32_t)__cvta_generic_to_shared(smem);
    uint32_t aoff[2], b1off[2], b3off[2];
    #pragma unroll
    for (int s = 0; s < 2; s++) {
        aoff[s]  = sbase + s*GSTG;
        b1off[s] = sbase + 2*GSTG + s*GSTG;
        b3off[s] = sbase + 4*GSTG + s*GSTG;
    }

    int lrow = tid >> 1;
    int lsg  = (tid & 1) * 4;
    const bf16* Arow; int szA = 16;
    {
        int gm = m0 + lrow;
        if (gm < M) Arow = A + (size_t)(sl[gm] >> 1) * DM;
        else { Arow = A; szA = 0; }
    }
    const bf16* B1row = B1 + (size_t)(n0 + lrow) * DM;
    const bf16* B3row = B3 + (size_t)(n0 + lrow) * DM;
    uint32_t dsw = (uint32_t)lrow * 128u;
    int rxor = lrow & 7;

    float ac1[4][4][4], ac3[4][4][4];
    #pragma unroll
    for (int i = 0; i < 4; i++)
        #pragma unroll
        for (int j = 0; j < 4; j++)
            #pragma unroll
            for (int q = 0; q < 4; q++) { ac1[i][j][q] = 0.f; ac3[i][j][q] = 0.f; }

    const int CC = DM / 64;
    auto loadChunk = [&](int c) {
        int s = c & 1;
        const char* pa  = (const char*)(Arow  + c*64);
        const char* pb1 = (const char*)(B1row + c*64);
        const char* pb3 = (const char*)(B3row + c*64);
        #pragma unroll
        for (int i = 0; i < 4; i++) {
            int seg = lsg + i;
            uint32_t o = dsw + (uint32_t)((seg ^ rxor) * 16);
            cpa(aoff[s]  + o, pa  + seg*16, szA);
            cpa(b1off[s] + o, pb1 + seg*16, 16);
            cpa(b3off[s] + o, pb3 + seg*16, 16);
        }
        asm volatile("cp.async.commit_group;" ::: "memory");
    };
    loadChunk(0);

    int lt = lane >> 3, rl = lane & 7;
    int th = (lt & 1) * 8;
    int ts = lane >> 4;

    for (int c = 0; c < CC; c++) {
        asm volatile("cp.async.wait_group 0;" ::: "memory");
        __syncthreads();
        if (c + 1 < CC) loadChunk(c + 1);

        uint32_t Ab = aoff[c & 1], B1b = b1off[c & 1], B3b = b3off[c & 1];
        #pragma unroll
        for (int kk = 0; kk < 4; kk++) {
            uint32_t af[4][4], f1[2][4], f3[2][4];
            #pragma unroll
            for (int i = 0; i < 4; i++) {
                int row = wm + i*16 + th + rl;
                int seg = 2*kk + ts;
                ldsm4(af[i], Ab + row*128 + ((seg ^ (row & 7)) << 4));
            }
            #pragma unroll
            for (int j = 0; j < 2; j++) {
                int nr = wn + j*16 + th + rl;
                int seg = 2*kk + ts;
                ldsm4(f1[j], B1b + nr*128 + ((seg ^ (nr & 7)) << 4));
                ldsm4(f3[j], B3b + nr*128 + ((seg ^ (nr & 7)) << 4));
            }
            #pragma unroll
            for (int i = 0; i < 4; i++)
                #pragma unroll
                for (int jn = 0; jn < 4; jn++) {
                    int jj = jn >> 1, hi = jn & 1;
                    mma_bf16(ac1[i][jn], af[i][0], af[i][1], af[i][2], af[i][3],
                             f1[jj][hi], f1[jj][hi+2]);
                    mma_bf16(ac3[i][jn], af[i][0], af[i][1], af[i][2], af[i][3],
                             f3[jj][hi], f3[jj][hi+2]);
                }
        }
    }

    int g = lane >> 2, tg = lane & 3;
    #pragma unroll
    for (int i = 0; i < 4; i++) {
        int r0 = m0 + wm + i*16 + g;
        int r1 = r0 + 8;
        bool v0 = r0 < M, v1 = r1 < M;
        int row0 = v0 ? sl[r0] : 0;
        int row1 = v1 ? sl[r1] : 0;
        #pragma unroll
        for (int j = 0; j < 4; j++) {
            int c0 = n0 + wn + j*8 + tg*2;
            if (v0) {
                float a0 = ac1[i][j][0], a1 = ac1[i][j][1];
                float u0 = a0 / (1.f + __expf(-a0)) * ac3[i][j][0];
                float u1 = a1 / (1.f + __expf(-a1)) * ac3[i][j][1];
                *(__nv_bfloat162*)(g_gb + (size_t)row0*NI + c0) = __floats2bfloat162_rn(u0, u1);
            }
            if (v1) {
                float a0 = ac1[i][j][2], a1 = ac1[i][j][3];
                float u0 = a0 / (1.f + __expf(-a0)) * ac3[i][j][2];
                float u1 = a1 / (1.f + __expf(-a1)) * ac3[i][j][3];
                *(__nv_bfloat162*)(g_gb + (size_t)row1*NI + c0) = __floats2bfloat162_rn(u0, u1);
            }
        }
    }
}

// ---------------- MoE w2 GEMM with fused scaled-atomic combine --------------
// C row = token (slot>>1); epilogue adds g_wslot[slot]*acc into out, which
// the WO GEMM pre-seeded with h. Two spread-address fp32 reductions/elem.
__global__ __launch_bounds__(256) void gemm_w2(
    const bf16* __restrict__ A, const bf16* __restrict__ B,
    float* __restrict__ out)
{
    extern __shared__ char smem[];
    int e = blockIdx.z;
    int M = g_cnt[e];
    if ((int)blockIdx.y * 128 >= M) return;
    const int* sl = g_slot + e * SEQ;
    B += (size_t)e * DM * NI;
    const int N = DM, K = NI;

    int m0 = blockIdx.y * 128, n0 = blockIdx.x * 128;
    int tid = threadIdx.x, warp = tid >> 5, lane = tid & 31;
    int wm = (warp >> 2) * 64, wn = (warp & 3) * 32;
    uint32_t sbase = (uint32_t)__cvta_generic_to_shared(smem);
    uint32_t aoff[3], boff[3];
    #pragma unroll
    for (int s = 0; s < 3; s++) {
        aoff[s] = sbase + s*GSTG;
        boff[s] = sbase + 3*GSTG + s*GSTG;
    }

    int lrow = tid >> 1;
    int lsg  = (tid & 1) * 4;
    const bf16* Arow; int szA = 16;
    {
        int gm = m0 + lrow;
        if (gm < M) Arow = A + (size_t)sl[gm] * K;
        else { Arow = A; szA = 0; }
    }
    const bf16* Brow = B + (size_t)(n0 + lrow) * K;
    uint32_t dsw = (uint32_t)lrow * 128u;
    int rxor = lrow & 7;

    float acc[4][4][4];
    #pragma unroll
    for (int i = 0; i < 4; i++)
        #pragma unroll
        for (int j = 0; j < 4; j++)
            #pragma unroll
            for (int q = 0; q < 4; q++) acc[i][j][q] = 0.f;

    int CC = K / 64;
    auto loadChunk = [&](int c) {
        int s = c % 3;
        const char* pa = (const char*)(Arow + c*64);
        const char* pb = (const char*)(Brow + c*64);
        #pragma unroll
        for (int i = 0; i < 4; i++) {
            int seg = lsg + i;
            uint32_t o = dsw + (uint32_t)((seg ^ rxor) * 16);
            cpa(aoff[s] + o, pa + seg*16, szA);
            cpa(boff[s] + o, pb + seg*16, 16);
        }
        asm volatile("cp.async.commit_group;" ::: "memory");
    };
    loadChunk(0);
    loadChunk(1);

    int lt = lane >> 3;
    int rl = lane & 7;
    int th = (lt & 1) * 8;
    int ts = lane >> 4;

    for (int c = 0; c < CC; c++) {
        if (c + 1 < CC) asm volatile("cp.async.wait_group 1;" ::: "memory");
        else            asm volatile("cp.async.wait_group 0;" ::: "memory");
        __syncthreads();
        if (c + 2 < CC) loadChunk(c + 2);

        uint32_t Ab = aoff[c % 3], Bb = boff[c % 3];
        #pragma unroll
        for (int kk = 0; kk < 4; kk++) {
            uint32_t af[4][4], bfm[2][4];
            #pragma unroll
            for (int i = 0; i < 4; i++) {
                int row = wm + i*16 + th + rl;
                int seg = 2*kk + ts;
                ldsm4(af[i], Ab + row*128 + ((seg ^ (row & 7)) << 4));
            }
            #pragma unroll
            for (int j = 0; j < 2; j++) {
                int nr = wn + j*16 + th + rl;
                int seg = 2*kk + ts;
                ldsm4(bfm[j], Bb + nr*128 + ((seg ^ (nr & 7)) << 4));
            }
            #pragma unroll
            for (int i = 0; i < 4; i++)
                #pragma unroll
                for (int jn = 0; jn < 4; jn++) {
                    int jj = jn >> 1, hi = jn & 1;
                    mma_bf16(acc[i][jn], af[i][0], af[i][1], af[i][2], af[i][3],
                             bfm[jj][hi], bfm[jj][hi+2]);
                }
        }
    }

    int g = lane >> 2, tg = lane & 3;
    #pragma unroll
    for (int i = 0; i < 4; i++) {
        int r0 = m0 + wm + i*16 + g;
        int r1 = r0 + 8;
        bool v0 = r0 < M, v1 = r1 < M;
        int slot0 = v0 ? sl[r0] : 0;
        int slot1 = v1 ? sl[r1] : 0;
        float w0 = v0 ? g_wslot[slot0] : 0.f;
        float w1 = v1 ? g_wslot[slot1] : 0.f;
        float* o0 = out + (size_t)(slot0 >> 1)*N;
        float* o1 = out + (size_t)(slot1 >> 1)*N;
        #pragma unroll
        for (int j = 0; j < 4; j++) {
            int c0 = n0 + wn + j*8 + tg*2;
            if (v0) {
                atomicAdd(o0 + c0,     w0 * acc[i][j][0]);
                atomicAdd(o0 + c0 + 1, w0 * acc[i][j][1]);
            }
            if (v1) {
                atomicAdd(o1 + c0,     w1 * acc[i][j][2]);
                atomicAdd(o1 + c0 + 1, w1 * acc[i][j][3]);
            }
        }
    }
}

// ---------------- attention v7: uniform-chunk split flash -------------------
#define ASTR 68
#define VSTR 72
__global__ __launch_bounds__(128) void attn6_kernel()
{
    __shared__ float Ks[64*ASTR];
    __shared__ bf16  Vt[64*VSTR];

    int qt = blockIdx.x, h = blockIdx.y, z = blockIdx.z;
    int kvh = h >> 2;
    int tid = threadIdx.x, warp = tid >> 5, lane = tid & 31;
    int g = lane >> 2, tg = lane & 3;
    int wq = warp * 16;
    int q0 = qt * 64;

    int n = qt + 1;
    int lo = z * CHUNK;
    int hi = min(n, lo + CHUNK);
    if (lo >= hi) return;   // empty chunk: no partial writes

    float oc[8][4];
    #pragma unroll
    for (int j = 0; j < 8; j++)
        #pragma unroll
        for (int q = 0; q < 4; q++) oc[j][q] = 0.f;
    float mrow[2] = {-1e30f, -1e30f};
    float lrow[2] = {0.f, 0.f};

    for (int i = tid; i < 64*16; i += 128) {
        int row = i >> 4, c4 = (i & 15) * 4;
        *(float4*)&Ks[row*ASTR + c4] =
            *(const float4*)(g_q + ((size_t)h*SEQ + q0 + row)*HDIM + c4);
    }
    __syncthreads();
    uint32_t aq[8][4];
    #pragma unroll
    for (int kk = 0; kk < 8; kk++) {
        aq[kk][0] = __float_as_uint(Ks[(wq+g)*ASTR + kk*8 + tg]);
        aq[kk][1] = __float_as_uint(Ks[(wq+g+8)*ASTR + kk*8 + tg]);
        aq[kk][2] = __float_as_uint(Ks[(wq+g)*ASTR + kk*8 + tg + 4]);
        aq[kk][3] = __float_as_uint(Ks[(wq+g+8)*ASTR + kk*8 + tg + 4]);
    }
    __syncthreads();

    for (int kt = lo; kt < hi; kt++) {
        for (int i = tid; i < 1024; i += 128) {
            int row = i >> 4, c4 = (i & 15) * 4;
            *(float4*)&Ks[row*ASTR + c4] =
                *(const float4*)(g_k + ((size_t)kvh*SEQ + kt*64 + row)*HDIM + c4);
        }
        for (int i = tid; i < 512; i += 128) {
            int row = i >> 3, seg = i & 7;
            *(uint4*)&Vt[row*VSTR + seg*8] =
                *(const uint4*)(g_vt + ((size_t)(kvh*HDIM + row))*SEQ + kt*64 + seg*8);
        }
        __syncthreads();

        float sc[8][4];
        #pragma unroll
        for (int j = 0; j < 8; j++)
            #pragma unroll
            for (int q = 0; q < 4; q++) sc[j][q] = 0.f;
        #pragma unroll
        for (int kk = 0; kk < 8; kk++) {
            #pragma unroll
            for (int j = 0; j < 8; j++) {
                uint32_t b0 = __float_as_uint(Ks[(j*8+g)*ASTR + kk*8 + tg]);
                uint32_t b1 = __float_as_uint(Ks[(j*8+g)*ASTR + kk*8 + tg + 4]);
                mma_tf32(sc[j], aq[kk][0], aq[kk][1], aq[kk][2], aq[kk][3], b0, b1);
            }
        }

        if (kt == qt) {
            int r0g = q0 + wq + g, r1g = r0g + 8;
            #pragma unroll
            for (int j = 0; j < 8; j++) {
                int c0 = kt*64 + j*8 + tg*2;
                if (c0     > r0g) sc[j][0] = -1e30f;
                if (c0 + 1 > r0g) sc[j][1] = -1e30f;
                if (c0     > r1g) sc[j][2] = -1e30f;
                if (c0 + 1 > r1g) sc[j][3] = -1e30f;
            }
        }

        float mx0 = -1e30f, mx1 = -1e30f;
        #pragma unroll
        for (int j = 0; j < 8; j++) {
            mx0 = fmaxf(mx0, fmaxf(sc[j][0], sc[j][1]));
            mx1 = fmaxf(mx1, fmaxf(sc[j][2], sc[j][3]));
        }
        mx0 = fmaxf(mx0, __shfl_xor_sync(0xffffffffu, mx0, 1));
        mx0 = fmaxf(mx0, __shfl_xor_sync(0xffffffffu, mx0, 2));
        mx1 = fmaxf(mx1, __shfl_xor_sync(0xffffffffu, mx1, 1));
        mx1 = fmaxf(mx1, __shfl_xor_sync(0xffffffffu, mx1, 2));
        float mn0 = fmaxf(mrow[0], mx0), mn1 = fmaxf(mrow[1], mx1);
        float s0 = __expf(mrow[0] - mn0), s1 = __expf(mrow[1] - mn1);
        float ls0 = 0.f, ls1 = 0.f;
        #pragma unroll
        for (int j = 0; j < 8; j++) {
            sc[j][0] = __expf(sc[j][0] - mn0);
            sc[j][1] = __expf(sc[j][1] - mn0);
            sc[j][2] = __expf(sc[j][2] - mn1);
            sc[j][3] = __expf(sc[j][3] - mn1);
            ls0 += sc[j][0] + sc[j][1];
            ls1 += sc[j][2] + sc[j][3];
        }
        ls0 += __shfl_xor_sync(0xffffffffu, ls0, 1);
        ls0 += __shfl_xor_sync(0xffffffffu, ls0, 2);
        ls1 += __shfl_xor_sync(0xffffffffu, ls1, 1);
        ls1 += __shfl_xor_sync(0xffffffffu, ls1, 2);
        lrow[0] = lrow[0]*s0 + ls0;
        lrow[1] = lrow[1]*s1 + ls1;
        mrow[0] = mn0; mrow[1] = mn1;
        #pragma unroll
        for (int j = 0; j < 8; j++) {
            oc[j][0] *= s0; oc[j][1] *= s0;
            oc[j][2] *= s1; oc[j][3] *= s1;
        }

        uint32_t pa[4][4];
        #pragma unroll
        for (int kk = 0; kk < 4; kk++) {
            pa[kk][0] = packbf(sc[2*kk][0],   sc[2*kk][1]);
            pa[kk][1] = packbf(sc[2*kk][2],   sc[2*kk][3]);
            pa[kk][2] = packbf(sc[2*kk+1][0], sc[2*kk+1][1]);
            pa[kk][3] = packbf(sc[2*kk+1][2], sc[2*kk+1][3]);
        }
        #pragma unroll
        for (int kk = 0; kk < 4; kk++) {
            #pragma unroll
            for (int j = 0; j < 8; j++) {
                uint32_t b0 = *(const uint32_t*)&Vt[(j*8+g)*VSTR + kk*16 + tg*2];
                uint32_t b1 = *(const uint32_t*)&Vt[(j*8+g)*VSTR + kk*16 + tg*2 + 8];
                mma_bf16(oc[j], pa[kk][0], pa[kk][1], pa[kk][2], pa[kk][3], b0, b1);
            }
        }
        __syncthreads();
    }

    size_t pb = (size_t)z * NH * SEQ;
    int r0 = q0 + wq + g, r1 = r0 + 8;
    size_t hr0 = (size_t)h*SEQ + r0, hr1 = (size_t)h*SEQ + r1;
    #pragma unroll
    for (int j = 0; j < 8; j++) {
        int c0 = j*8 + tg*2;
        float2 v0; v0.x = oc[j][0]; v0.y = oc[j][1];
        float2 v1; v1.x = oc[j][2]; v1.y = oc[j][3];
        *(float2*)&g_po[(pb + hr0)*HDIM + c0] = v0;
        *(float2*)&g_po[(pb + hr1)*HDIM + c0] = v1;
    }
    if (tg == 0) {
        g_pm[pb + hr0] = mrow[0];
        g_pm[pb + hr1] = mrow[1];
        g_pl[pb + hr0] = lrow[0];
        g_pl[pb + hr1] = lrow[1];
    }
}

// ---------------- split reduce: fold only live chunks -> y_bf ---------------
__global__ void attn_reduce_kernel()
{
    int i = blockIdx.x * blockDim.x + threadIdx.x;
    if (i >= NH*SEQ*(HDIM/2)) return;
    int hrow = i >> 5;
    int c2 = (i & 31) * 2;
    int h = hrow / SEQ, row = hrow % SEQ;
    int qt = row >> 6;
    int nch = (qt + 1 + CHUNK - 1) / CHUNK;
    float M = -1e30f;
    float ms[NSPLIT], ls[NSPLIT];
    for (int s = 0; s < nch; s++) {
        ms[s] = g_pm[s*NH*SEQ + hrow];
        ls[s] = g_pl[s*NH*SEQ + hrow];
        M = fmaxf(M, ms[s]);
    }
    float den = 0.f, vx = 0.f, vy = 0.f;
    for (int s = 0; s < nch; s++) {
        float w = __expf(ms[s] - M);
        den += ls[s] * w;
        float2 o = *(const float2*)&g_po[((size_t)s*NH*SEQ + hrow)*HDIM + c2];
        vx += o.x * w;
        vy += o.y * w;
    }
    float inv = 1.f / den;
    *(__nv_bfloat162*)(g_y_bf + (size_t)row*DM + h*HDIM + c2) =
        __floats2bfloat162_rn(vx*inv, vy*inv);
}

// ---------------- host launch ----------------------------------------------
#define GEMM_SMEM (6*GSTG)
#define W13_SMEM  (6*GSTG)

extern "C" void kernel_launch(void* const* d_in, const int* in_sizes, int n_in,
                              void* d_out, int out_size)
{
    const float* x      = (const float*)d_in[0];
    const float* wqkv   = (const float*)d_in[1];
    const float* wo     = (const float*)d_in[2];
    const float* gate_w = (const float*)d_in[3];
    const float* w1     = (const float*)d_in[4];
    const float* w2     = (const float*)d_in[5];
    const float* w3     = (const float*)d_in[6];
    const float* anw    = (const float*)d_in[7];
    const float* fnw    = (const float*)d_in[8];
    const float* freqs  = (const float*)d_in[9];
    float* out = (float*)d_out;

    bf16 *p_wqkv_bf, *p_wo_bf, *p_w1_bf, *p_w3_bf, *p_w2_bf;
    bf16 *p_hn_bf, *p_hf_bf, *p_y_bf, *p_gb;
    float *p_h;
    int *p_cnt;
    cudaGetSymbolAddress((void**)&p_wqkv_bf, g_wqkv_bf);
    cudaGetSymbolAddress((void**)&p_wo_bf,   g_wo_bf);
    cudaGetSymbolAddress((void**)&p_w1_bf,   g_w1_bf);
    cudaGetSymbolAddress((void**)&p_w3_bf,   g_w3_bf);
    cudaGetSymbolAddress((void**)&p_w2_bf,   g_w2_bf);
    cudaGetSymbolAddress((void**)&p_hn_bf,   g_hn_bf);
    cudaGetSymbolAddress((void**)&p_hf_bf,   g_hf_bf);
    cudaGetSymbolAddress((void**)&p_y_bf,    g_y_bf);
    cudaGetSymbolAddress((void**)&p_gb,      g_gb);
    cudaGetSymbolAddress((void**)&p_h,       g_h);
    cudaGetSymbolAddress((void**)&p_cnt,     g_cnt);

    static cudaStream_t s2 = nullptr;
    static cudaEvent_t ev0 = nullptr, ev1 = nullptr;
    static bool attr_set = false;
    if (!attr_set) {
        cudaFuncSetAttribute(gemm_bf,
            cudaFuncAttributeMaxDynamicSharedMemorySize, GEMM_SMEM);
        cudaFuncSetAttribute(gemm_w2,
            cudaFuncAttributeMaxDynamicSharedMemorySize, GEMM_SMEM);
        cudaFuncSetAttribute(gemm_qkv,
            cudaFuncAttributeMaxDynamicSharedMemorySize, GEMM_SMEM);
        cudaFuncSetAttribute(gemm_w13,
            cudaFuncAttributeMaxDynamicSharedMemorySize, W13_SMEM);
        cudaStreamCreateWithFlags(&s2, cudaStreamNonBlocking);
        cudaEventCreateWithFlags(&ev0, cudaEventDisableTiming);
        cudaEventCreateWithFlags(&ev1, cudaEventDisableTiming);
        attr_set = true;
    }

    // (1) wqkv convert (main)
    {
        int n4 = QKVN*DM/4;
        f2bf_kernel<<<(n4+255)/256, 256>>>((const float4*)wqkv, (uint2*)p_wqkv_bf, n4);
    }
    // (2,3) fork first two big MoE converts on side stream
    cudaEventRecord(ev0, 0);
    cudaStreamWaitEvent(s2, ev0, 0);
    {
        int n4 = (int)((size_t)NE*NI*DM/4);
        f2bf_kernel<<<(n4+255)/256, 256, 0, s2>>>((const float4*)w1, (uint2*)p_w1_bf, n4);
        f2bf_kernel<<<(n4+255)/256, 256, 0, s2>>>((const float4*)w3, (uint2*)p_w3_bf, n4);
    }
    // (4) attn rmsnorm
    rmsnorm_kernel<<<SEQ, 256>>>(x, anw, p_hn_bf);
    // (5) qkv GEMM + fused RoPE
    gemm_qkv<<<dim3(QKVN/128, SEQ/128), 256, GEMM_SMEM>>>(p_hn_bf, p_wqkv_bf, freqs);
    // (6) attention v7 (live chunks only)
    attn6_kernel<<<dim3(SEQ/64, NH, NSPLIT), 128>>>();
    // (7+) rest
    {
        int n4 = (int)((size_t)NE*NI*DM/4);
        f2bf_kernel<<<(n4+255)/256, 256, 0, s2>>>((const float4*)w2, (uint2*)p_w2_bf, n4);
    }
    cudaEventRecord(ev1, s2);
    {
        int n4 = DM*DM/4;
        f2bf_kernel<<<(n4+255)/256, 256>>>((const float4*)wo, (uint2*)p_wo_bf, n4);
    }
    attn_reduce_kernel<<<(NH*SEQ*(HDIM/2) + 255)/256, 256>>>();
    // WO GEMM: h = x + y@wo^T, dual-stored to g_h AND out (seeds residual)
    gemm_bf<<<dim3(DM/128, SEQ/128), 256, GEMM_SMEM>>>(
        p_y_bf, p_wo_bf, x, p_h, out, SEQ, DM, DM);
    // fused ffn rmsnorm + gating (cnt cleared first)
    cudaMemsetAsync(p_cnt, 0, NE*sizeof(int), 0);
    rmsnorm_gate_kernel<<<SEQ, 256>>>(p_h, fnw, gate_w, p_hf_bf);

    cudaStreamWaitEvent(0, ev1, 0);
    gemm_w13<<<dim3(NI/128, SEQ/128, NE), 256, W13_SMEM>>>(
        p_hf_bf, p_w1_bf, p_w3_bf);
    // w2 GEMM with fused scaled-atomic combine into out
    gemm_w2<<<dim3(DM/128, SEQ/128, NE), 256, GEMM_SMEM>>>(
        p_gb, p_w2_bf, out);
}

// round 17
// speedup vs baseline: 1.0065x; 1.0065x over previous
#include <cuda_runtime.h>
#include <cuda_bf16.h>
#include <math.h>
#include <stdint.h>

#define SEQ 2048
#define DM 1024
#define NH 16
#define NKV 4
#define HDIM 64
#define NE 8
#define NI 3584
#define QKVN 1536
#define NSLOTS (2*SEQ)
#define NSPLIT 8
#define CHUNK 4

typedef __nv_bfloat16 bf16;

// ---------------- scratch (device globals; no allocations) ----------------
__device__ bf16  g_wqkv_bf[QKVN*DM];
__device__ bf16  g_wo_bf[DM*DM];
__device__ bf16  g_w1_bf[(size_t)NE*NI*DM];
__device__ bf16  g_w3_bf[(size_t)NE*NI*DM];
__device__ bf16  g_w2_bf[(size_t)NE*DM*NI];
__device__ bf16  g_hn_bf[SEQ*DM];
__device__ float g_q[NH*SEQ*HDIM];      // tf32-rounded, pre-scaled 0.125
__device__ float g_k[NKV*SEQ*HDIM];     // tf32-rounded
__device__ bf16  g_vt[NKV*HDIM*SEQ];    // bf16, transposed [kvh][d][t]
__device__ float g_po[(size_t)NSPLIT*NH*SEQ*HDIM];
__device__ float g_pm[NSPLIT*NH*SEQ];
__device__ float g_pl[NSPLIT*NH*SEQ];
__device__ bf16  g_y_bf[SEQ*DM];
__device__ float g_h[SEQ*DM];
__device__ bf16  g_hf_bf[SEQ*DM];
__device__ int   g_cnt[NE];
__device__ int   g_slot[NE*SEQ];
__device__ float g_wslot[NSLOTS];
__device__ bf16  g_gb[(size_t)NSLOTS*NI];
__device__ float g_os[(size_t)NSLOTS*DM];

// ---------------- helpers ---------------------------------------------------
__device__ __forceinline__ uint32_t f2tf32(float f) {
    uint32_t r;
    asm("cvt.rna.tf32.f32 %0, %1;" : "=r"(r) : "f"(f));
    return r;
}
__device__ __forceinline__ void mma_tf32(float c[4],
    uint32_t a0, uint32_t a1, uint32_t a2, uint32_t a3,
    uint32_t b0, uint32_t b1)
{
    asm volatile(
        "mma.sync.aligned.m16n8k8.row.col.f32.tf32.tf32.f32 "
        "{%0,%1,%2,%3}, {%4,%5,%6,%7}, {%8,%9}, {%0,%1,%2,%3};"
        : "+f"(c[0]), "+f"(c[1]), "+f"(c[2]), "+f"(c[3])
        : "r"(a0), "r"(a1), "r"(a2), "r"(a3), "r"(b0), "r"(b1));
}
__device__ __forceinline__ void mma_bf16(float c[4],
    uint32_t a0, uint32_t a1, uint32_t a2, uint32_t a3,
    uint32_t b0, uint32_t b1)
{
    asm volatile(
        "mma.sync.aligned.m16n8k16.row.col.f32.bf16.bf16.f32 "
        "{%0,%1,%2,%3}, {%4,%5,%6,%7}, {%8,%9}, {%0,%1,%2,%3};"
        : "+f"(c[0]), "+f"(c[1]), "+f"(c[2]), "+f"(c[3])
        : "r"(a0), "r"(a1), "r"(a2), "r"(a3), "r"(b0), "r"(b1));
}
__device__ __forceinline__ void ldsm4(uint32_t r[4], uint32_t addr) {
    asm volatile("ldmatrix.sync.aligned.m8n8.x4.shared.b16 {%0,%1,%2,%3}, [%4];"
                 : "=r"(r[0]), "=r"(r[1]), "=r"(r[2]), "=r"(r[3]) : "r"(addr));
}
__device__ __forceinline__ void cpa(uint32_t dst, const void* src, int sz) {
    asm volatile("cp.async.cg.shared.global [%0], [%1], 16, %2;"
                 :: "r"(dst), "l"(src), "r"(sz));
}
__device__ __forceinline__ uint32_t packbf(float a, float b) {
    __nv_bfloat162 p = __floats2bfloat162_rn(a, b);
    return *(uint32_t*)&p;
}

// ---------------- fp32 -> bf16 convert --------------------------------------
__global__ void f2bf_kernel(const float4* __restrict__ s, uint2* __restrict__ d, int n4)
{
    int i = blockIdx.x * blockDim.x + threadIdx.x;
    if (i >= n4) return;
    float4 v = s[i];
    __nv_bfloat162 lo = __floats2bfloat162_rn(v.x, v.y);
    __nv_bfloat162 hi = __floats2bfloat162_rn(v.z, v.w);
    uint2 o;
    o.x = *(uint32_t*)&lo;
    o.y = *(uint32_t*)&hi;
    d[i] = o;
}

// ---------------- rmsnorm (bf16 out) ----------------------------------------
__global__ __launch_bounds__(256) void rmsnorm_kernel(
    const float* __restrict__ x, const float* __restrict__ w,
    bf16* __restrict__ obf)
{
    int row = blockIdx.x;
    int tid = threadIdx.x;
    const float4* xr = (const float4*)(x + (size_t)row*DM);
    float4 v = xr[tid];
    float ss = v.x*v.x + v.y*v.y + v.z*v.z + v.w*v.w;
    __shared__ float red[8];
    #pragma unroll
    for (int ofs = 16; ofs > 0; ofs >>= 1) ss += __shfl_down_sync(0xffffffffu, ss, ofs);
    if ((tid & 31) == 0) red[tid >> 5] = ss;
    __syncthreads();
    __shared__ float sr;
    if (tid == 0) {
        float t = 0.f;
        #pragma unroll
        for (int i = 0; i < 8; i++) t += red[i];
        sr = rsqrtf(t / (float)DM + 1e-5f);
    }
    __syncthreads();
    float r = sr;
    float4 wv = ((const float4*)w)[tid];
    float4 o;
    o.x = v.x*r*wv.x; o.y = v.y*r*wv.y; o.z = v.z*r*wv.z; o.w = v.w*r*wv.w;
    __nv_bfloat162 lo = __floats2bfloat162_rn(o.x, o.y);
    __nv_bfloat162 hi = __floats2bfloat162_rn(o.z, o.w);
    uint2 ob; ob.x = *(uint32_t*)&lo; ob.y = *(uint32_t*)&hi;
    *(uint2*)(obf + (size_t)row*DM + tid*4) = ob;
}

// ---------------- fused ffn rmsnorm + gating --------------------------------
__global__ __launch_bounds__(256) void rmsnorm_gate_kernel(
    const float* __restrict__ x, const float* __restrict__ w,
    const float* __restrict__ gw, bf16* __restrict__ obf)
{
    int row = blockIdx.x;
    int tid = threadIdx.x;
    const float4* xr = (const float4*)(x + (size_t)row*DM);
    float4 v = xr[tid];
    float ss = v.x*v.x + v.y*v.y + v.z*v.z + v.w*v.w;
    __shared__ float red[8];
    #pragma unroll
    for (int ofs = 16; ofs > 0; ofs >>= 1) ss += __shfl_down_sync(0xffffffffu, ss, ofs);
    if ((tid & 31) == 0) red[tid >> 5] = ss;
    __syncthreads();
    __shared__ float sr;
    if (tid == 0) {
        float t = 0.f;
        #pragma unroll
        for (int i = 0; i < 8; i++) t += red[i];
        sr = rsqrtf(t / (float)DM + 1e-5f);
    }
    __syncthreads();
    float r = sr;
    float4 wv = ((const float4*)w)[tid];
    float4 o;
    o.x = v.x*r*wv.x; o.y = v.y*r*wv.y; o.z = v.z*r*wv.z; o.w = v.w*r*wv.w;
    __nv_bfloat162 lo = __floats2bfloat162_rn(o.x, o.y);
    __nv_bfloat162 hi = __floats2bfloat162_rn(o.z, o.w);
    uint2 ob; ob.x = *(uint32_t*)&lo; ob.y = *(uint32_t*)&hi;
    *(uint2*)(obf + (size_t)row*DM + tid*4) = ob;

    float d[NE];
    #pragma unroll
    for (int e = 0; e < NE; e++) {
        float4 gv = ((const float4*)(gw + (size_t)e*DM))[tid];
        d[e] = o.x*gv.x + o.y*gv.y + o.z*gv.z + o.w*gv.w;
    }
    #pragma unroll
    for (int e = 0; e < NE; e++) {
        #pragma unroll
        for (int ofs = 16; ofs > 0; ofs >>= 1)
            d[e] += __shfl_down_sync(0xffffffffu, d[e], ofs);
    }
    __shared__ float red2[8][NE];
    if ((tid & 31) == 0) {
        #pragma unroll
        for (int e = 0; e < NE; e++) red2[tid >> 5][e] = d[e];
    }
    __syncthreads();
    if (tid == 0) {
        float lg[NE];
        #pragma unroll
        for (int e = 0; e < NE; e++) {
            float t = 0.f;
            #pragma unroll
            for (int wpi = 0; wpi < 8; wpi++) t += red2[wpi][e];
            lg[e] = t;
        }
        float mx = lg[0];
        #pragma unroll
        for (int i = 1; i < NE; i++) mx = fmaxf(mx, lg[i]);
        float p[NE]; float den = 0.f;
        #pragma unroll
        for (int i = 0; i < NE; i++) { p[i] = expf(lg[i]-mx); den += p[i]; }
        #pragma unroll
        for (int i = 0; i < NE; i++) p[i] /= den;
        int i1 = 0;
        #pragma unroll
        for (int i = 1; i < NE; i++) if (p[i] > p[i1]) i1 = i;
        int i2 = (i1 == 0) ? 1 : 0;
        #pragma unroll
        for (int i = 0; i < NE; i++) if (i != i1 && p[i] > p[i2]) i2 = i;
        float w1 = p[i1], w2 = p[i2];
        float sw2 = w1 + w2;
        w1 /= sw2; w2 /= sw2;
        int pos1 = atomicAdd(&g_cnt[i1], 1);
        g_slot[i1*SEQ + pos1] = 2*row;
        g_wslot[2*row] = w1;
        int pos2 = atomicAdd(&g_cnt[i2], 1);
        g_slot[i2*SEQ + pos2] = 2*row + 1;
        g_wslot[2*row+1] = w2;
    }
}

// ---------------- bf16 HMMA GEMM: C[M,N] = A @ B^T (+resid) ----------------
#define GSTG 16384
template<bool GATHER>
__global__ __launch_bounds__(256) void gemm_bf(
    const bf16* __restrict__ A, const bf16* __restrict__ B,
    const float* __restrict__ resid, float* __restrict__ C,
    int M, int N, int K, int shiftA)
{
    extern __shared__ char smem[];
    const int* sl = nullptr;
    if (GATHER) {
        int e = blockIdx.z;
        M = g_cnt[e];
        if ((int)blockIdx.y * 128 >= M) return;
        sl = g_slot + e * SEQ;
        B += (size_t)e * N * K;
    }
    int m0 = blockIdx.y * 128, n0 = blockIdx.x * 128;
    int tid = threadIdx.x, warp = tid >> 5, lane = tid & 31;
    int wm = (warp >> 2) * 64, wn = (warp & 3) * 32;
    uint32_t sbase = (uint32_t)__cvta_generic_to_shared(smem);
    uint32_t aoff[3], boff[3];
    #pragma unroll
    for (int s = 0; s < 3; s++) {
        aoff[s] = sbase + s*GSTG;
        boff[s] = sbase + 3*GSTG + s*GSTG;
    }

    int lrow = tid >> 1;
    int lsg  = (tid & 1) * 4;
    const bf16* Arow; int szA = 16;
    if (GATHER) {
        int gm = m0 + lrow;
        if (gm < M) Arow = A + (size_t)(sl[gm] >> shiftA) * K;
        else { Arow = A; szA = 0; }
    } else {
        Arow = A + (size_t)(m0 + lrow) * K;
    }
    const bf16* Brow = B + (size_t)(n0 + lrow) * K;
    uint32_t dsw = (uint32_t)lrow * 128u;
    int rxor = lrow & 7;

    float acc[4][4][4];
    #pragma unroll
    for (int i = 0; i < 4; i++)
        #pragma unroll
        for (int j = 0; j < 4; j++)
            #pragma unroll
            for (int q = 0; q < 4; q++) acc[i][j][q] = 0.f;

    int CC = K / 64;
    auto loadChunk = [&](int c) {
        int s = c % 3;
        const char* pa = (const char*)(Arow + c*64);
        const char* pb = (const char*)(Brow + c*64);
        #pragma unroll
        for (int i = 0; i < 4; i++) {
            int seg = lsg + i;
            uint32_t o = dsw + (uint32_t)((seg ^ rxor) * 16);
            cpa(aoff[s] + o, pa + seg*16, szA);
            cpa(boff[s] + o, pb + seg*16, 16);
        }
        asm volatile("cp.async.commit_group;" ::: "memory");
    };
    loadChunk(0);
    if (CC > 1) loadChunk(1);

    int lt = lane >> 3;
    int rl = lane & 7;
    int th = (lt & 1) * 8;
    int ts = lane >> 4;

    for (int c = 0; c < CC; c++) {
        if (c + 1 < CC) asm volatile("cp.async.wait_group 1;" ::: "memory");
        else            asm volatile("cp.async.wait_group 0;" ::: "memory");
        __syncthreads();
        if (c + 2 < CC) loadChunk(c + 2);

        uint32_t Ab = aoff[c % 3], Bb = boff[c % 3];
        #pragma unroll
        for (int kk = 0; kk < 4; kk++) {
            uint32_t af[4][4], bfm[2][4];
            #pragma unroll
            for (int i = 0; i < 4; i++) {
                int row = wm + i*16 + th + rl;
                int seg = 2*kk + ts;
                ldsm4(af[i], Ab + row*128 + ((seg ^ (row & 7)) << 4));
            }
            #pragma unroll
            for (int j = 0; j < 2; j++) {
                int nr = wn + j*16 + th + rl;
                int seg = 2*kk + ts;
                ldsm4(bfm[j], Bb + nr*128 + ((seg ^ (nr & 7)) << 4));
            }
            #pragma unroll
            for (int i = 0; i < 4; i++)
                #pragma unroll
                for (int jn = 0; jn < 4; jn++) {
                    int jj = jn >> 1, hi = jn & 1;
                    mma_bf16(acc[i][jn], af[i][0], af[i][1], af[i][2], af[i][3],
                             bfm[jj][hi], bfm[jj][hi+2]);
                }
        }
    }

    int g = lane >> 2, tg = lane & 3;
    #pragma unroll
    for (int i = 0; i < 4; i++) {
        int r0 = m0 + wm + i*16 + g;
        int r1 = r0 + 8;
        bool v0, v1;
        int row0, row1;
        if (GATHER) {
            v0 = r0 < M; v1 = r1 < M;
            row0 = v0 ? sl[r0] : 0;
            row1 = v1 ? sl[r1] : 0;
        } else {
            v0 = v1 = true; row0 = r0; row1 = r1;
        }
        #pragma unroll
        for (int j = 0; j < 4; j++) {
            int c0 = n0 + wn + j*8 + tg*2;
            if (v0) {
                float2 v; v.x = acc[i][j][0]; v.y = acc[i][j][1];
                if (resid) {
                    v.x += resid[(size_t)row0*N + c0];
                    v.y += resid[(size_t)row0*N + c0 + 1];
                }
                *(float2*)(C + (size_t)row0*N + c0) = v;
            }
            if (v1) {
                float2 v; v.x = acc[i][j][2]; v.y = acc[i][j][3];
                if (resid) {
                    v.x += resid[(size_t)row1*N + c0];
                    v.y += resid[(size_t)row1*N + c0 + 1];
                }
                *(float2*)(C + (size_t)row1*N + c0) = v;
            }
        }
    }
}

// ---------------- QKV GEMM with fused RoPE/split epilogue -------------------
__device__ __forceinline__ void rope_write(
    int t, int c0, float vx, float vy, const float* __restrict__ freqs)
{
    if (c0 < DM) {
        int h = c0 >> 6, d = c0 & 63, p = d >> 1;
        float cs = freqs[((size_t)t*32 + p)*2 + 0];
        float sn = freqs[((size_t)t*32 + p)*2 + 1];
        float2 o;
        o.x = __uint_as_float(f2tf32((vx*cs - vy*sn) * 0.125f));
        o.y = __uint_as_float(f2tf32((vy*cs + vx*sn) * 0.125f));
        *(float2*)(g_q + ((size_t)h*SEQ + t)*HDIM + d) = o;
    } else if (c0 < DM + NKV*HDIM) {
        int c = c0 - DM;
        int kh = c >> 6, d = c & 63, p = d >> 1;
        float cs = freqs[((size_t)t*32 + p)*2 + 0];
        float sn = freqs[((size_t)t*32 + p)*2 + 1];
        float2 o;
        o.x = __uint_as_float(f2tf32(vx*cs - vy*sn));
        o.y = __uint_as_float(f2tf32(vy*cs + vx*sn));
        *(float2*)(g_k + ((size_t)kh*SEQ + t)*HDIM + d) = o;
    } else {
        int c = c0 - DM - NKV*HDIM;
        int vh = c >> 6, d = c & 63;
        g_vt[((size_t)(vh*HDIM + d  ))*SEQ + t] = __float2bfloat16(vx);
        g_vt[((size_t)(vh*HDIM + d+1))*SEQ + t] = __float2bfloat16(vy);
    }
}

__global__ __launch_bounds__(256) void gemm_qkv(
    const bf16* __restrict__ A, const bf16* __restrict__ B,
    const float* __restrict__ freqs)
{
    extern __shared__ char smem[];
    const int K = DM;
    int m0 = blockIdx.y * 128, n0 = blockIdx.x * 128;
    int tid = threadIdx.x, warp = tid >> 5, lane = tid & 31;
    int wm = (warp >> 2) * 64, wn = (warp & 3) * 32;
    uint32_t sbase = (uint32_t)__cvta_generic_to_shared(smem);
    uint32_t aoff[3], boff[3];
    #pragma unroll
    for (int s = 0; s < 3; s++) {
        aoff[s] = sbase + s*GSTG;
        boff[s] = sbase + 3*GSTG + s*GSTG;
    }

    int lrow = tid >> 1;
    int lsg  = (tid & 1) * 4;
    const bf16* Arow = A + (size_t)(m0 + lrow) * K;
    const bf16* Brow = B + (size_t)(n0 + lrow) * K;
    uint32_t dsw = (uint32_t)lrow * 128u;
    int rxor = lrow & 7;

    float acc[4][4][4];
    #pragma unroll
    for (int i = 0; i < 4; i++)
        #pragma unroll
        for (int j = 0; j < 4; j++)
            #pragma unroll
            for (int q = 0; q < 4; q++) acc[i][j][q] = 0.f;

    const int CC = K / 64;
    auto loadChunk = [&](int c) {
        int s = c % 3;
        const char* pa = (const char*)(Arow + c*64);
        const char* pb = (const char*)(Brow + c*64);
        #pragma unroll
        for (int i = 0; i < 4; i++) {
            int seg = lsg + i;
            uint32_t o = dsw + (uint32_t)((seg ^ rxor) * 16);
            cpa(aoff[s] + o, pa + seg*16, 16);
            cpa(boff[s] + o, pb + seg*16, 16);
        }
        asm volatile("cp.async.commit_group;" ::: "memory");
    };
    loadChunk(0);
    loadChunk(1);

    int lt = lane >> 3;
    int rl = lane & 7;
    int th = (lt & 1) * 8;
    int ts = lane >> 4;

    for (int c = 0; c < CC; c++) {
        if (c + 1 < CC) asm volatile("cp.async.wait_group 1;" ::: "memory");
        else            asm volatile("cp.async.wait_group 0;" ::: "memory");
        __syncthreads();
        if (c + 2 < CC) loadChunk(c + 2);

        uint32_t Ab = aoff[c % 3], Bb = boff[c % 3];
        #pragma unroll
        for (int kk = 0; kk < 4; kk++) {
            uint32_t af[4][4], bfm[2][4];
            #pragma unroll
            for (int i = 0; i < 4; i++) {
                int row = wm + i*16 + th + rl;
                int seg = 2*kk + ts;
                ldsm4(af[i], Ab + row*128 + ((seg ^ (row & 7)) << 4));
            }
            #pragma unroll
            for (int j = 0; j < 2; j++) {
                int nr = wn + j*16 + th + rl;
                int seg = 2*kk + ts;
                ldsm4(bfm[j], Bb + nr*128 + ((seg ^ (nr & 7)) << 4));
            }
            #pragma unroll
            for (int i = 0; i < 4; i++)
                #pragma unroll
                for (int jn = 0; jn < 4; jn++) {
                    int jj = jn >> 1, hi = jn & 1;
                    mma_bf16(acc[i][jn], af[i][0], af[i][1], af[i][2], af[i][3],
                             bfm[jj][hi], bfm[jj][hi+2]);
                }
        }
    }

    int g = lane >> 2, tg = lane & 3;
    #pragma unroll
    for (int i = 0; i < 4; i++) {
        int t0 = m0 + wm + i*16 + g;
        int t1 = t0 + 8;
        #pragma unroll
        for (int j = 0; j < 4; j++) {
            int c0 = n0 + wn + j*8 + tg*2;
            rope_write(t0, c0, acc[i][j][0], acc[i][j][1], freqs);
            rope_write(t1, c0, acc[i][j][2], acc[i][j][3], freqs);
        }
    }
}

// ---------------- fused MoE w1/w3 GEMM + silu*mul (bf16 out) ---------------
__global__ __launch_bounds__(256) void gemm_w13(
    const bf16* __restrict__ A, const bf16* __restrict__ B1,
    const bf16* __restrict__ B3)
{
    extern __shared__ char smem[];
    int e = blockIdx.z;
    int M = g_cnt[e];
    if ((int)blockIdx.y * 128 >= M) return;
    const int* sl = g_slot + e * SEQ;
    B1 += (size_t)e * NI * DM;
    B3 += (size_t)e * NI * DM;

    int m0 = blockIdx.y * 128, n0 = blockIdx.x * 128;
    int tid = threadIdx.x, warp = tid >> 5, lane = tid & 31;
    int wm = (warp >> 2) * 64, wn = (warp & 3) * 32;
    uint32_t sbase = (uint32_t)__cvta_generic_to_shared(smem);
    uint32_t aoff[2], b1off[2], b3off[2];
    #pragma unroll
    for (int s = 0; s < 2; s++) {
        aoff[s]  = sbase + s*GSTG;
        b1off[s] = sbase + 2*GSTG + s*GSTG;
        b3off[s] = sbase + 4*GSTG + s*GSTG;
    }

    int lrow = tid >> 1;
    int lsg  = (tid & 1) * 4;
    const bf16* Arow; int szA = 16;
    {
        int gm = m0 + lrow;
        if (gm < M) Arow = A + (size_t)(sl[gm] >> 1) * DM;
        else { Arow = A; szA = 0; }
    }
    const bf16* B1row = B1 + (size_t)(n0 + lrow) * DM;
    const bf16* B3row = B3 + (size_t)(n0 + lrow) * DM;
    uint32_t dsw = (uint32_t)lrow * 128u;
    int rxor = lrow & 7;

    float ac1[4][4][4], ac3[4][4][4];
    #pragma unroll
    for (int i = 0; i < 4; i++)
        #pragma unroll
        for (int j = 0; j < 4; j++)
            #pragma unroll
            for (int q = 0; q < 4; q++) { ac1[i][j][q] = 0.f; ac3[i][j][q] = 0.f; }

    const int CC = DM / 64;
    auto loadChunk = [&](int c) {
        int s = c & 1;
        const char* pa  = (const char*)(Arow  + c*64);
        const char* pb1 = (const char*)(B1row + c*64);
        const char* pb3 = (const char*)(B3row + c*64);
        #pragma unroll
        for (int i = 0; i < 4; i++) {
            int seg = lsg + i;
            uint32_t o = dsw + (uint32_t)((seg ^ rxor) * 16);
            cpa(aoff[s]  + o, pa  + seg*16, szA);
            cpa(b1off[s] + o, pb1 + seg*16, 16);
            cpa(b3off[s] + o, pb3 + seg*16, 16);
        }
        asm volatile("cp.async.commit_group;" ::: "memory");
    };
    loadChunk(0);

    int lt = lane >> 3, rl = lane & 7;
    int th = (lt & 1) * 8;
    int ts = lane >> 4;

    for (int c = 0; c < CC; c++) {
        asm volatile("cp.async.wait_group 0;" ::: "memory");
        __syncthreads();
        if (c + 1 < CC) loadChunk(c + 1);

        uint32_t Ab = aoff[c & 1], B1b = b1off[c & 1], B3b = b3off[c & 1];
        #pragma unroll
        for (int kk = 0; kk < 4; kk++) {
            uint32_t af[4][4], f1[2][4], f3[2][4];
            #pragma unroll
            for (int i = 0; i < 4; i++) {
                int row = wm + i*16 + th + rl;
                int seg = 2*kk + ts;
                ldsm4(af[i], Ab + row*128 + ((seg ^ (row & 7)) << 4));
            }
            #pragma unroll
            for (int j = 0; j < 2; j++) {
                int nr = wn + j*16 + th + rl;
                int seg = 2*kk + ts;
                ldsm4(f1[j], B1b + nr*128 + ((seg ^ (nr & 7)) << 4));
                ldsm4(f3[j], B3b + nr*128 + ((seg ^ (nr & 7)) << 4));
            }
            #pragma unroll
            for (int i = 0; i < 4; i++)
                #pragma unroll
                for (int jn = 0; jn < 4; jn++) {
                    int jj = jn >> 1, hi = jn & 1;
                    mma_bf16(ac1[i][jn], af[i][0], af[i][1], af[i][2], af[i][3],
                             f1[jj][hi], f1[jj][hi+2]);
                    mma_bf16(ac3[i][jn], af[i][0], af[i][1], af[i][2], af[i][3],
                             f3[jj][hi], f3[jj][hi+2]);
                }
        }
    }

    int g = lane >> 2, tg = lane & 3;
    #pragma unroll
    for (int i = 0; i < 4; i++) {
        int r0 = m0 + wm + i*16 + g;
        int r1 = r0 + 8;
        bool v0 = r0 < M, v1 = r1 < M;
        int row0 = v0 ? sl[r0] : 0;
        int row1 = v1 ? sl[r1] : 0;
        #pragma unroll
        for (int j = 0; j < 4; j++) {
            int c0 = n0 + wn + j*8 + tg*2;
            if (v0) {
                float a0 = ac1[i][j][0], a1 = ac1[i][j][1];
                float u0 = a0 / (1.f + __expf(-a0)) * ac3[i][j][0];
                float u1 = a1 / (1.f + __expf(-a1)) * ac3[i][j][1];
                *(__nv_bfloat162*)(g_gb + (size_t)row0*NI + c0) = __floats2bfloat162_rn(u0, u1);
            }
            if (v1) {
                float a0 = ac1[i][j][2], a1 = ac1[i][j][3];
                float u0 = a0 / (1.f + __expf(-a0)) * ac3[i][j][2];
                float u1 = a1 / (1.f + __expf(-a1)) * ac3[i][j][3];
                *(__nv_bfloat162*)(g_gb + (size_t)row1*NI + c0) = __floats2bfloat162_rn(u0, u1);
            }
        }
    }
}

// ---------------- attention v7: uniform-chunk split flash -------------------
#define ASTR 68
#define VSTR 72
__global__ __launch_bounds__(128) void attn6_kernel()
{
    __shared__ float Ks[64*ASTR];
    __shared__ bf16  Vt[64*VSTR];

    int qt = blockIdx.x, h = blockIdx.y, z = blockIdx.z;
    int kvh = h >> 2;
    int tid = threadIdx.x, warp = tid >> 5, lane = tid & 31;
    int g = lane >> 2, tg = lane & 3;
    int wq = warp * 16;
    int q0 = qt * 64;

    int n = qt + 1;
    int lo = z * CHUNK;
    int hi = min(n, lo + CHUNK);
    if (lo >= hi) return;   // empty chunk: no partial writes

    float oc[8][4];
    #pragma unroll
    for (int j = 0; j < 8; j++)
        #pragma unroll
        for (int q = 0; q < 4; q++) oc[j][q] = 0.f;
    float mrow[2] = {-1e30f, -1e30f};
    float lrow[2] = {0.f, 0.f};

    for (int i = tid; i < 64*16; i += 128) {
        int row = i >> 4, c4 = (i & 15) * 4;
        *(float4*)&Ks[row*ASTR + c4] =
            *(const float4*)(g_q + ((size_t)h*SEQ + q0 + row)*HDIM + c4);
    }
    __syncthreads();
    uint32_t aq[8][4];
    #pragma unroll
    for (int kk = 0; kk < 8; kk++) {
        aq[kk][0] = __float_as_uint(Ks[(wq+g)*ASTR + kk*8 + tg]);
        aq[kk][1] = __float_as_uint(Ks[(wq+g+8)*ASTR + kk*8 + tg]);
        aq[kk][2] = __float_as_uint(Ks[(wq+g)*ASTR + kk*8 + tg + 4]);
        aq[kk][3] = __float_as_uint(Ks[(wq+g+8)*ASTR + kk*8 + tg + 4]);
    }
    __syncthreads();

    for (int kt = lo; kt < hi; kt++) {
        for (int i = tid; i < 1024; i += 128) {
            int row = i >> 4, c4 = (i & 15) * 4;
            *(float4*)&Ks[row*ASTR + c4] =
                *(const float4*)(g_k + ((size_t)kvh*SEQ + kt*64 + row)*HDIM + c4);
        }
        for (int i = tid; i < 512; i += 128) {
            int row = i >> 3, seg = i & 7;
            *(uint4*)&Vt[row*VSTR + seg*8] =
                *(const uint4*)(g_vt + ((size_t)(kvh*HDIM + row))*SEQ + kt*64 + seg*8);
        }
        __syncthreads();

        float sc[8][4];
        #pragma unroll
        for (int j = 0; j < 8; j++)
            #pragma unroll
            for (int q = 0; q < 4; q++) sc[j][q] = 0.f;
        #pragma unroll
        for (int kk = 0; kk < 8; kk++) {
            #pragma unroll
            for (int j = 0; j < 8; j++) {
                uint32_t b0 = __float_as_uint(Ks[(j*8+g)*ASTR + kk*8 + tg]);
                uint32_t b1 = __float_as_uint(Ks[(j*8+g)*ASTR + kk*8 + tg + 4]);
                mma_tf32(sc[j], aq[kk][0], aq[kk][1], aq[kk][2], aq[kk][3], b0, b1);
            }
        }

        if (kt == qt) {
            int r0g = q0 + wq + g, r1g = r0g + 8;
            #pragma unroll
            for (int j = 0; j < 8; j++) {
                int c0 = kt*64 + j*8 + tg*2;
                if (c0     > r0g) sc[j][0] = -1e30f;
                if (c0 + 1 > r0g) sc[j][1] = -1e30f;
                if (c0     > r1g) sc[j][2] = -1e30f;
                if (c0 + 1 > r1g) sc[j][3] = -1e30f;
            }
        }

        float mx0 = -1e30f, mx1 = -1e30f;
        #pragma unroll
        for (int j = 0; j < 8; j++) {
            mx0 = fmaxf(mx0, fmaxf(sc[j][0], sc[j][1]));
            mx1 = fmaxf(mx1, fmaxf(sc[j][2], sc[j][3]));
        }
        mx0 = fmaxf(mx0, __shfl_xor_sync(0xffffffffu, mx0, 1));
        mx0 = fmaxf(mx0, __shfl_xor_sync(0xffffffffu, mx0, 2));
        mx1 = fmaxf(mx1, __shfl_xor_sync(0xffffffffu, mx1, 1));
        mx1 = fmaxf(mx1, __shfl_xor_sync(0xffffffffu, mx1, 2));
        float mn0 = fmaxf(mrow[0], mx0), mn1 = fmaxf(mrow[1], mx1);
        float s0 = __expf(mrow[0] - mn0), s1 = __expf(mrow[1] - mn1);
        float ls0 = 0.f, ls1 = 0.f;
        #pragma unroll
        for (int j = 0; j < 8; j++) {
            sc[j][0] = __expf(sc[j][0] - mn0);
            sc[j][1] = __expf(sc[j][1] - mn0);
            sc[j][2] = __expf(sc[j][2] - mn1);
            sc[j][3] = __expf(sc[j][3] - mn1);
            ls0 += sc[j][0] + sc[j][1];
            ls1 += sc[j][2] + sc[j][3];
        }
        ls0 += __shfl_xor_sync(0xffffffffu, ls0, 1);
        ls0 += __shfl_xor_sync(0xffffffffu, ls0, 2);
        ls1 += __shfl_xor_sync(0xffffffffu, ls1, 1);
        ls1 += __shfl_xor_sync(0xffffffffu, ls1, 2);
        lrow[0] = lrow[0]*s0 + ls0;
        lrow[1] = lrow[1]*s1 + ls1;
        mrow[0] = mn0; mrow[1] = mn1;
        #pragma unroll
        for (int j = 0; j < 8; j++) {
            oc[j][0] *= s0; oc[j][1] *= s0;
            oc[j][2] *= s1; oc[j][3] *= s1;
        }

        uint32_t pa[4][4];
        #pragma unroll
        for (int kk = 0; kk < 4; kk++) {
            pa[kk][0] = packbf(sc[2*kk][0],   sc[2*kk][1]);
            pa[kk][1] = packbf(sc[2*kk][2],   sc[2*kk][3]);
            pa[kk][2] = packbf(sc[2*kk+1][0], sc[2*kk+1][1]);
            pa[kk][3] = packbf(sc[2*kk+1][2], sc[2*kk+1][3]);
        }
        #pragma unroll
        for (int kk = 0; kk < 4; kk++) {
            #pragma unroll
            for (int j = 0; j < 8; j++) {
                uint32_t b0 = *(const uint32_t*)&Vt[(j*8+g)*VSTR + kk*16 + tg*2];
                uint32_t b1 = *(const uint32_t*)&Vt[(j*8+g)*VSTR + kk*16 + tg*2 + 8];
                mma_bf16(oc[j], pa[kk][0], pa[kk][1], pa[kk][2], pa[kk][3], b0, b1);
            }
        }
        __syncthreads();
    }

    size_t pb = (size_t)z * NH * SEQ;
    int r0 = q0 + wq + g, r1 = r0 + 8;
    size_t hr0 = (size_t)h*SEQ + r0, hr1 = (size_t)h*SEQ + r1;
    #pragma unroll
    for (int j = 0; j < 8; j++) {
        int c0 = j*8 + tg*2;
        float2 v0; v0.x = oc[j][0]; v0.y = oc[j][1];
        float2 v1; v1.x = oc[j][2]; v1.y = oc[j][3];
        *(float2*)&g_po[(pb + hr0)*HDIM + c0] = v0;
        *(float2*)&g_po[(pb + hr1)*HDIM + c0] = v1;
    }
    if (tg == 0) {
        g_pm[pb + hr0] = mrow[0];
        g_pm[pb + hr1] = mrow[1];
        g_pl[pb + hr0] = lrow[0];
        g_pl[pb + hr1] = lrow[1];
    }
}

// ---------------- split reduce: fold only live chunks -> y_bf ---------------
__global__ void attn_reduce_kernel()
{
    int i = blockIdx.x * blockDim.x + threadIdx.x;
    if (i >= NH*SEQ*(HDIM/2)) return;
    int hrow = i >> 5;
    int c2 = (i & 31) * 2;
    int h = hrow / SEQ, row = hrow % SEQ;
    int qt = row >> 6;
    int nch = (qt + 1 + CHUNK - 1) / CHUNK;
    float M = -1e30f;
    float ms[NSPLIT], ls[NSPLIT];
    for (int s = 0; s < nch; s++) {
        ms[s] = g_pm[s*NH*SEQ + hrow];
        ls[s] = g_pl[s*NH*SEQ + hrow];
        M = fmaxf(M, ms[s]);
    }
    float den = 0.f, vx = 0.f, vy = 0.f;
    for (int s = 0; s < nch; s++) {
        float w = __expf(ms[s] - M);
        den += ls[s] * w;
        float2 o = *(const float2*)&g_po[((size_t)s*NH*SEQ + hrow)*HDIM + c2];
        vx += o.x * w;
        vy += o.y * w;
    }
    float inv = 1.f / den;
    *(__nv_bfloat162*)(g_y_bf + (size_t)row*DM + h*HDIM + c2) =
        __floats2bfloat162_rn(vx*inv, vy*inv);
}

// ---------------- final combine ---------------------------------------------
__global__ __launch_bounds__(256) void combine_kernel(float* __restrict__ out)
{
    int t = blockIdx.x;
    int tid = threadIdx.x;
    float w0 = g_wslot[2*t], w1 = g_wslot[2*t+1];
    float4 hv = ((const float4*)(g_h + (size_t)t*DM))[tid];
    float4 a = ((const float4*)(g_os + (size_t)(2*t)*DM))[tid];
    float4 b = ((const float4*)(g_os + (size_t)(2*t+1)*DM))[tid];
    float4 o;
    o.x = hv.x + w0*a.x + w1*b.x;
    o.y = hv.y + w0*a.y + w1*b.y;
    o.z = hv.z + w0*a.z + w1*b.z;
    o.w = hv.w + w0*a.w + w1*b.w;
    ((float4*)(out + (size_t)t*DM))[tid] = o;
}

// ---------------- host launch ----------------------------------------------
#define GEMM_SMEM (6*GSTG)
#define W13_SMEM  (6*GSTG)

extern "C" void kernel_launch(void* const* d_in, const int* in_sizes, int n_in,
                              void* d_out, int out_size)
{
    const float* x      = (const float*)d_in[0];
    const float* wqkv   = (const float*)d_in[1];
    const float* wo     = (const float*)d_in[2];
    const float* gate_w = (const float*)d_in[3];
    const float* w1     = (const float*)d_in[4];
    const float* w2     = (const float*)d_in[5];
    const float* w3     = (const float*)d_in[6];
    const float* anw    = (const float*)d_in[7];
    const float* fnw    = (const float*)d_in[8];
    const float* freqs  = (const float*)d_in[9];
    float* out = (float*)d_out;

    bf16 *p_wqkv_bf, *p_wo_bf, *p_w1_bf, *p_w3_bf, *p_w2_bf;
    bf16 *p_hn_bf, *p_hf_bf, *p_y_bf, *p_gb;
    float *p_h, *p_os;
    int *p_cnt;
    cudaGetSymbolAddress((void**)&p_wqkv_bf, g_wqkv_bf);
    cudaGetSymbolAddress((void**)&p_wo_bf,   g_wo_bf);
    cudaGetSymbolAddress((void**)&p_w1_bf,   g_w1_bf);
    cudaGetSymbolAddress((void**)&p_w3_bf,   g_w3_bf);
    cudaGetSymbolAddress((void**)&p_w2_bf,   g_w2_bf);
    cudaGetSymbolAddress((void**)&p_hn_bf,   g_hn_bf);
    cudaGetSymbolAddress((void**)&p_hf_bf,   g_hf_bf);
    cudaGetSymbolAddress((void**)&p_y_bf,    g_y_bf);
    cudaGetSymbolAddress((void**)&p_gb,      g_gb);
    cudaGetSymbolAddress((void**)&p_h,       g_h);
    cudaGetSymbolAddress((void**)&p_os,      g_os);
    cudaGetSymbolAddress((void**)&p_cnt,     g_cnt);

    static cudaStream_t s2 = nullptr;
    static cudaEvent_t ev0 = nullptr, ev1 = nullptr;
    static bool attr_set = false;
    if (!attr_set) {
        cudaFuncSetAttribute(gemm_bf<false>,
            cudaFuncAttributeMaxDynamicSharedMemorySize, GEMM_SMEM);
        cudaFuncSetAttribute(gemm_bf<true>,
            cudaFuncAttributeMaxDynamicSharedMemorySize, GEMM_SMEM);
        cudaFuncSetAttribute(gemm_qkv,
            cudaFuncAttributeMaxDynamicSharedMemorySize, GEMM_SMEM);
        cudaFuncSetAttribute(gemm_w13,
            cudaFuncAttributeMaxDynamicSharedMemorySize, W13_SMEM);
        cudaStreamCreateWithFlags(&s2, cudaStreamNonBlocking);
        cudaEventCreateWithFlags(&ev0, cudaEventDisableTiming);
        cudaEventCreateWithFlags(&ev1, cudaEventDisableTiming);
        attr_set = true;
    }

    // (1) wqkv convert (main)
    {
        int n4 = QKVN*DM/4;
        f2bf_kernel<<<(n4+255)/256, 256>>>((const float4*)wqkv, (uint2*)p_wqkv_bf, n4);
    }
    // (2,3) fork first two big MoE converts on side stream
    cudaEventRecord(ev0, 0);
    cudaStreamWaitEvent(s2, ev0, 0);
    {
        int n4 = (int)((size_t)NE*NI*DM/4);
        f2bf_kernel<<<(n4+255)/256, 256, 0, s2>>>((const float4*)w1, (uint2*)p_w1_bf, n4);
        f2bf_kernel<<<(n4+255)/256, 256, 0, s2>>>((const float4*)w3, (uint2*)p_w3_bf, n4);
    }
    // (4) attn rmsnorm
    rmsnorm_kernel<<<SEQ, 256>>>(x, anw, p_hn_bf);
    // (5) qkv GEMM + fused RoPE
    gemm_qkv<<<dim3(QKVN/128, SEQ/128), 256, GEMM_SMEM>>>(p_hn_bf, p_wqkv_bf, freqs);
    // (6) attention v7 (live chunks only)
    attn6_kernel<<<dim3(SEQ/64, NH, NSPLIT), 128>>>();
    // (7+) rest
    {
        int n4 = (int)((size_t)NE*NI*DM/4);
        f2bf_kernel<<<(n4+255)/256, 256, 0, s2>>>((const float4*)w2, (uint2*)p_w2_bf, n4);
    }
    cudaEventRecord(ev1, s2);
    {
        int n4 = DM*DM/4;
        f2bf_kernel<<<(n4+255)/256, 256>>>((const float4*)wo, (uint2*)p_wo_bf, n4);
    }
    attn_reduce_kernel<<<(NH*SEQ*(HDIM/2) + 255)/256, 256>>>();
    gemm_bf<false><<<dim3(DM/128, SEQ/128), 256, GEMM_SMEM>>>(
        p_y_bf, p_wo_bf, x, p_h, SEQ, DM, DM, 0);
    // fused ffn rmsnorm + gating (cnt cleared first)
    cudaMemsetAsync(p_cnt, 0, NE*sizeof(int), 0);
    rmsnorm_gate_kernel<<<SEQ, 256>>>(p_h, fnw, gate_w, p_hf_bf);

    cudaStreamWaitEvent(0, ev1, 0);
    gemm_w13<<<dim3(NI/128, SEQ/128, NE), 256, W13_SMEM>>>(
        p_hf_bf, p_w1_bf, p_w3_bf);
    gemm_bf<true><<<dim3(DM/128, SEQ/128, NE), 256, GEMM_SMEM>>>(
        p_gb, p_w2_bf, nullptr, p_os, 0, DM, NI, 0);
    combine_kernel<<<SEQ, 256>>>(out);
}